// round 14
// baseline (speedup 1.0000x reference)
#include <cuda_runtime.h>
#include <cuda_fp16.h>
#include <cstdint>

#define N_NODES 50000
#define N_EDGES 800000
#define FEAT    1024
#define EMB     128

// ---------------------------------------------------------------------------
// Device-global scratch
// ---------------------------------------------------------------------------
__device__ float  g_h[(size_t)N_NODES * EMB];     // h = x @ W^T   (25.6 MB)
__device__ __half g_wh16[(size_t)EMB * FEAT];     // W split hi (fp16)
__device__ __half g_wl16[(size_t)EMB * FEAT];     // W split lo (fp16)
__device__ int    g_cnt[N_NODES];                 // degree counters
__device__ int    g_off[N_NODES + 1];             // CSR offsets
__device__ int2   g_edge[N_EDGES];                // bucketed (col, val-bits)

// ---------------------------------------------------------------------------
// helpers
// ---------------------------------------------------------------------------
__device__ __forceinline__ void split16(float v, __half& hi, __half& lo) {
    hi = __float2half_rn(v);
    lo = __float2half_rn(v - __half2float(hi));
}

__device__ __forceinline__ void mma16(float d[4], const uint32_t a[4],
                                      uint32_t b0, uint32_t b1) {
    asm volatile(
        "mma.sync.aligned.m16n8k16.row.col.f32.f16.f16.f32 "
        "{%0,%1,%2,%3}, {%4,%5,%6,%7}, {%8,%9}, {%0,%1,%2,%3};"
        : "+f"(d[0]), "+f"(d[1]), "+f"(d[2]), "+f"(d[3])
        : "r"(a[0]), "r"(a[1]), "r"(a[2]), "r"(a[3]), "r"(b0), "r"(b1));
}

// ---------------------------------------------------------------------------
// split W once into fp16 hi/lo
// ---------------------------------------------------------------------------
__global__ void split_w_kernel(const float* __restrict__ w) {
    int i = blockIdx.x * blockDim.x + threadIdx.x;
    if (i < EMB * FEAT) {
        __half h, l;
        split16(w[i], h, l);
        g_wh16[i] = h;
        g_wl16[i] = l;
    }
}

// ---------------------------------------------------------------------------
// GEMM: h = x @ W^T via mma.sync fp16, 2-pass split (xh*wh + xh*wl).
// CTA tile 64x128 (M halved vs R12): acc 32 regs/thread -> 3 CTAs/SM
// = 24 warps/SM for latency hiding (occupancy was the untouched knob).
// 256 threads = 8 warps (2M x 4N), warp tile 32x32. KC=32, 16 k-iters... 32.
// ---------------------------------------------------------------------------
#define SH  40               // half-elements row stride in smem (conflict-free)
#define KC  32
#define NKIT (FEAT / KC)     // 32
#define BM  64

__global__ __launch_bounds__(256, 3)
void gemm_fp16_mma(const float* __restrict__ x) {
    __shared__ __half axh[BM  * SH];   // 64 x 32 (5 KB)
    __shared__ __half swh[128 * SH];   // 128 x 32 (10 KB)
    __shared__ __half swl[128 * SH];   // 10 KB

    const int tid  = threadIdx.x;
    const int m0   = blockIdx.x * BM;
    const int wid  = tid >> 5;
    const int lane = tid & 31;
    const int wm   = (wid & 1) * 32;    // 2 M-groups
    const int wn   = (wid >> 1) * 32;   // 4 N-groups
    const int g    = lane >> 2;
    const int t    = lane & 3;

    // x load mapping: 4 threads per row, 8 floats each
    const int xr = tid >> 2;            // 0..63
    const int xk = (tid & 3) * 8;       // 0,8,16,24
    const int gxr = m0 + xr;
    const bool xok = (gxr < N_NODES);
    const float* xrow = x + (size_t)(xok ? gxr : 0) * FEAT;

    // w load mapping: 2 threads per row, 16 halves each
    const int wr = tid >> 1;            // 0..127
    const int wk = (tid & 1) * 16;
    const __half* whrow = g_wh16 + (size_t)wr * FEAT;
    const __half* wlrow = g_wl16 + (size_t)wr * FEAT;

    float acc[2][4][4];
#pragma unroll
    for (int mi = 0; mi < 2; mi++)
#pragma unroll
        for (int ni = 0; ni < 4; ni++)
#pragma unroll
            for (int j = 0; j < 4; j++) acc[mi][ni][j] = 0.f;

    float4 xb[2];
    uint4  whb[2], wlb[2];

    // ---- prologue prefetch: chunk 0 ----
    xb[0] = xok ? *(const float4*)(xrow + xk)     : make_float4(0.f,0.f,0.f,0.f);
    xb[1] = xok ? *(const float4*)(xrow + xk + 4) : make_float4(0.f,0.f,0.f,0.f);
    whb[0] = *(const uint4*)(whrow + wk);
    whb[1] = *(const uint4*)(whrow + wk + 8);
    wlb[0] = *(const uint4*)(wlrow + wk);
    wlb[1] = *(const uint4*)(wlrow + wk + 8);

    for (int it = 0; it < NKIT; ++it) {
        __syncthreads();   // previous iter's frag reads done

        // convert x -> fp16 and store; store pre-split w
        {
            __half h[8];
            const float* xf = (const float*)xb;
#pragma unroll
            for (int j = 0; j < 8; j++) h[j] = __float2half_rn(xf[j]);
            *(uint4*)(axh + xr * SH + xk) = *(const uint4*)h;
            __half* pwh = swh + wr * SH + wk;
            __half* pwl = swl + wr * SH + wk;
            *(uint4*)(pwh)     = whb[0];
            *(uint4*)(pwh + 8) = whb[1];
            *(uint4*)(pwl)     = wlb[0];
            *(uint4*)(pwl + 8) = wlb[1];
        }
        __syncthreads();

        // prefetch next chunk (overlaps MMA section)
        if (it + 1 < NKIT) {
            const int k0 = (it + 1) * KC;
            xb[0] = xok ? *(const float4*)(xrow + k0 + xk)
                        : make_float4(0.f,0.f,0.f,0.f);
            xb[1] = xok ? *(const float4*)(xrow + k0 + xk + 4)
                        : make_float4(0.f,0.f,0.f,0.f);
            whb[0] = *(const uint4*)(whrow + k0 + wk);
            whb[1] = *(const uint4*)(whrow + k0 + wk + 8);
            wlb[0] = *(const uint4*)(wlrow + k0 + wk);
            wlb[1] = *(const uint4*)(wlrow + k0 + wk + 8);
        }

        // 2 k-steps of k=16 (scalar LDS fragment loads)
#pragma unroll
        for (int ks = 0; ks < 2; ks++) {
            const int k0 = ks * 16;
            uint32_t ah[2][4];
#pragma unroll
            for (int mi = 0; mi < 2; mi++) {
                const int r = wm + mi * 16;
                const __half* bh = axh + k0 + 2 * t;
                ah[mi][0] = *(const uint32_t*)(bh + (r + g)     * SH);
                ah[mi][1] = *(const uint32_t*)(bh + (r + g + 8) * SH);
                ah[mi][2] = *(const uint32_t*)(bh + (r + g)     * SH + 8);
                ah[mi][3] = *(const uint32_t*)(bh + (r + g + 8) * SH + 8);
            }
#pragma unroll
            for (int ni = 0; ni < 4; ni++) {
                const int n = wn + ni * 8 + g;
                uint32_t bh0 = *(const uint32_t*)(swh + n * SH + k0 + 2 * t);
                uint32_t bh1 = *(const uint32_t*)(swh + n * SH + k0 + 2 * t + 8);
                uint32_t bl0 = *(const uint32_t*)(swl + n * SH + k0 + 2 * t);
                uint32_t bl1 = *(const uint32_t*)(swl + n * SH + k0 + 2 * t + 8);
#pragma unroll
                for (int mi = 0; mi < 2; mi++) {
                    mma16(acc[mi][ni], ah[mi], bh0, bh1);   // xh*wh
                    mma16(acc[mi][ni], ah[mi], bl0, bl1);   // xh*wl
                }
            }
        }
    }

    // epilogue
#pragma unroll
    for (int mi = 0; mi < 2; mi++) {
#pragma unroll
        for (int ni = 0; ni < 4; ni++) {
            const int r = m0 + wm + mi * 16 + g;
            const int c = wn + ni * 8 + 2 * t;
            if (r < N_NODES)
                *(float2*)(g_h + (size_t)r * EMB + c) =
                    make_float2(acc[mi][ni][0], acc[mi][ni][1]);
            if (r + 8 < N_NODES)
                *(float2*)(g_h + (size_t)(r + 8) * EMB + c) =
                    make_float2(acc[mi][ni][2], acc[mi][ni][3]);
        }
    }
}

// ---------------------------------------------------------------------------
// CSR build: memset(g_cnt) -> hist -> fused scan -> bucket
// ---------------------------------------------------------------------------
__global__ void hist_kernel(const int* __restrict__ row) {
    int e = blockIdx.x * blockDim.x + threadIdx.x;
    if (e < N_EDGES) atomicAdd(&g_cnt[row[e]], 1);
}

#define SCAN_T 1024
#define SCAN_CHUNK ((N_NODES + SCAN_T - 1) / SCAN_T)   // 49

__global__ __launch_bounds__(SCAN_T)
void scan_fused_kernel() {
    __shared__ int s[SCAN_T];
    const int tid = threadIdx.x;
    const int beg = tid * SCAN_CHUNK;
    const int end = min(beg + SCAN_CHUNK, N_NODES);

    int sum = 0;
    for (int i = beg; i < end; i++) sum += g_cnt[i];
    s[tid] = sum;
    __syncthreads();
#pragma unroll
    for (int d = 1; d < SCAN_T; d <<= 1) {
        int tmp = (tid >= d) ? s[tid - d] : 0;
        __syncthreads();
        s[tid] += tmp;
        __syncthreads();
    }
    int run = s[tid] - sum;
    for (int i = beg; i < end; i++) {
        int c = g_cnt[i];
        g_off[i] = run;
        run += c;
        g_cnt[i] = 0;
    }
    if (tid == 0) g_off[N_NODES] = N_EDGES;
}

__global__ void bucket_kernel(const int* __restrict__ row,
                              const int* __restrict__ col,
                              const float* __restrict__ vals) {
    int e = blockIdx.x * blockDim.x + threadIdx.x;
    if (e < N_EDGES) {
        int r = row[e];
        int pos = g_off[r] + atomicAdd(&g_cnt[r], 1);
        g_edge[pos] = make_int2(col[e], __float_as_int(vals[e]));
    }
}

// ---------------------------------------------------------------------------
// Gather: one warp per destination node; atomic-free, writes out once.
// ---------------------------------------------------------------------------
__global__ void gather_kernel(float* __restrict__ out) {
    const int lane = threadIdx.x & 31;
    const int node = (blockIdx.x * blockDim.x + threadIdx.x) >> 5;
    if (node >= N_NODES) return;

    const int beg = g_off[node];
    const int end = g_off[node + 1];

    float4 acc = make_float4(0.f, 0.f, 0.f, 0.f);
    for (int e = beg; e < end; e++) {
        const int2 ev = g_edge[e];
        const float v = __int_as_float(ev.y);
        const float4 hv = __ldg((const float4*)(g_h + (size_t)ev.x * EMB) + lane);
        acc.x = fmaf(v, hv.x, acc.x);
        acc.y = fmaf(v, hv.y, acc.y);
        acc.z = fmaf(v, hv.z, acc.z);
        acc.w = fmaf(v, hv.w, acc.w);
    }
    *((float4*)(out + (size_t)node * EMB) + lane) = acc;
}

// ---------------------------------------------------------------------------
// Launch: R12 structure (fork-join CSR build on side stream).
// ---------------------------------------------------------------------------
extern "C" void kernel_launch(void* const* d_in, const int* in_sizes, int n_in,
                              void* d_out, int out_size) {
    const float* x    = (const float*)d_in[0];
    const float* w    = (const float*)d_in[1];
    const int*   row  = (const int*)  d_in[2];
    const int*   col  = (const int*)  d_in[3];
    const float* vals = (const float*)d_in[4];
    float*       out  = (float*)d_out;

    static cudaStream_t s_side = nullptr;
    static cudaEvent_t  ev_fork = nullptr, ev_join = nullptr;
    if (s_side == nullptr) {
        cudaStreamCreateWithFlags(&s_side, cudaStreamNonBlocking);
        cudaEventCreateWithFlags(&ev_fork, cudaEventDisableTiming);
        cudaEventCreateWithFlags(&ev_join, cudaEventDisableTiming);
    }

    int* cnt_ptr = nullptr;
    cudaGetSymbolAddress((void**)&cnt_ptr, g_cnt);

    // (1) main: split W
    split_w_kernel<<<(EMB * FEAT + 255) / 256, 256>>>(w);

    // fork side stream
    cudaEventRecord(ev_fork, 0);
    cudaStreamWaitEvent(s_side, ev_fork, 0);

    // side: CSR build
    cudaMemsetAsync(cnt_ptr, 0, N_NODES * sizeof(int), s_side);
    hist_kernel<<<(N_EDGES + 255) / 256, 256, 0, s_side>>>(row);
    scan_fused_kernel<<<1, SCAN_T, 0, s_side>>>();
    bucket_kernel<<<(N_EDGES + 255) / 256, 256, 0, s_side>>>(row, col, vals);
    cudaEventRecord(ev_join, s_side);

    // main: GEMM (64x128 tiles, 782 CTAs, occ=3)
    gemm_fp16_mma<<<(N_NODES + BM - 1) / BM, 256>>>(x);

    // join, then gather
    cudaStreamWaitEvent(0, ev_join, 0);
    gather_kernel<<<(N_NODES * 32 + 255) / 256, 256>>>(out);
}

// round 15
// speedup vs baseline: 1.4840x; 1.4840x over previous
#include <cuda_runtime.h>
#include <cuda_fp16.h>
#include <cstdint>

#define N_NODES 50000
#define N_EDGES 800000
#define FEAT    1024
#define EMB     128

// ---------------------------------------------------------------------------
// Device-global scratch
// ---------------------------------------------------------------------------
__device__ float  g_h[(size_t)N_NODES * EMB];     // h accumulator (25.6 MB)
__device__ __half g_wh16[(size_t)EMB * FEAT];     // W split hi (fp16)
__device__ __half g_wl16[(size_t)EMB * FEAT];     // W split lo (fp16)
__device__ int    g_cnt[N_NODES];                 // degree counters
__device__ int    g_off[N_NODES + 1];             // CSR offsets
__device__ int    g_part[128];                    // scan partials
__device__ int2   g_edge[N_EDGES];                // bucketed (col, val-bits)

// ---------------------------------------------------------------------------
// helpers
// ---------------------------------------------------------------------------
__device__ __forceinline__ void split16(float v, __half& hi, __half& lo) {
    hi = __float2half_rn(v);
    lo = __float2half_rn(v - __half2float(hi));
}

__device__ __forceinline__ void mma16(float d[4], const uint32_t a[4],
                                      uint32_t b0, uint32_t b1) {
    asm volatile(
        "mma.sync.aligned.m16n8k16.row.col.f32.f16.f16.f32 "
        "{%0,%1,%2,%3}, {%4,%5,%6,%7}, {%8,%9}, {%0,%1,%2,%3};"
        : "+f"(d[0]), "+f"(d[1]), "+f"(d[2]), "+f"(d[3])
        : "r"(a[0]), "r"(a[1]), "r"(a[2]), "r"(a[3]), "r"(b0), "r"(b1));
}

// ---------------------------------------------------------------------------
// split W once into fp16 hi/lo
// ---------------------------------------------------------------------------
__global__ void split_w_kernel(const float* __restrict__ w) {
    int i = blockIdx.x * blockDim.x + threadIdx.x;
    if (i < EMB * FEAT) {
        __half h, l;
        split16(w[i], h, l);
        g_wh16[i] = h;
        g_wl16[i] = l;
    }
}

// ---------------------------------------------------------------------------
// GEMM: h += x[:, khalf] @ W[:, khalf]^T  (K split in 2; g_h pre-zeroed).
// Champion inner loop (R12) verbatim; NKIT 32 -> 16 per CTA.
// blockIdx.x: bit0 = K-half, rest = M-tile. Grid 782, occ 2.
// ---------------------------------------------------------------------------
#define SH  40               // half-elements row stride in smem (conflict-free)
#define KC  32
#define KHALF 512
#define NKIT (KHALF / KC)    // 16

__global__ __launch_bounds__(256, 2)
void gemm_fp16_mma(const float* __restrict__ x) {
    __shared__ __half axh[128 * SH];
    __shared__ __half swh[128 * SH];
    __shared__ __half swl[128 * SH];

    const int tid  = threadIdx.x;
    const int mt   = blockIdx.x >> 1;
    const int kb   = (blockIdx.x & 1) * KHALF;
    const int m0   = mt * 128;
    const int wid  = tid >> 5;
    const int lane = tid & 31;
    const int wm   = (wid & 3) * 32;    // warp M offset
    const int wn   = (wid >> 2) * 64;   // warp N offset
    const int g    = lane >> 2;
    const int t    = lane & 3;

    const int lrow = tid >> 1;
    const int lk   = (tid & 1) * 16;
    const int gxr  = m0 + lrow;
    const bool xok = (gxr < N_NODES);
    const float* xrow = x + (size_t)(xok ? gxr : 0) * FEAT + kb;
    const __half* whrow = g_wh16 + (size_t)lrow * FEAT + kb;
    const __half* wlrow = g_wl16 + (size_t)lrow * FEAT + kb;

    float acc[2][8][4];
#pragma unroll
    for (int mi = 0; mi < 2; mi++)
#pragma unroll
        for (int ni = 0; ni < 8; ni++)
#pragma unroll
            for (int j = 0; j < 4; j++) acc[mi][ni][j] = 0.f;

    float4 xb[4];
    uint4  whb[2], wlb[2];

    // ---- prologue prefetch: chunk 0 ----
#pragma unroll
    for (int j = 0; j < 4; j++)
        xb[j] = xok ? *(const float4*)(xrow + lk + j * 4)
                    : make_float4(0.f, 0.f, 0.f, 0.f);
    whb[0] = *(const uint4*)(whrow + lk);
    whb[1] = *(const uint4*)(whrow + lk + 8);
    wlb[0] = *(const uint4*)(wlrow + lk);
    wlb[1] = *(const uint4*)(wlrow + lk + 8);

    for (int it = 0; it < NKIT; ++it) {
        __syncthreads();   // previous iter's frag reads done

        // convert x -> fp16 (hi only) and store; store pre-split w
        {
            __half h[16];
            const float* xf = (const float*)xb;
#pragma unroll
            for (int j = 0; j < 16; j++) h[j] = __float2half_rn(xf[j]);
            __half* pxh = axh + lrow * SH + lk;
            *(uint4*)(pxh)     = *(const uint4*)(h);
            *(uint4*)(pxh + 8) = *(const uint4*)(h + 8);
            __half* pwh = swh + lrow * SH + lk;
            __half* pwl = swl + lrow * SH + lk;
            *(uint4*)(pwh)     = whb[0];
            *(uint4*)(pwh + 8) = whb[1];
            *(uint4*)(pwl)     = wlb[0];
            *(uint4*)(pwl + 8) = wlb[1];
        }
        __syncthreads();

        // prefetch next chunk (overlaps MMA section)
        if (it + 1 < NKIT) {
            const int k0 = (it + 1) * KC;
#pragma unroll
            for (int j = 0; j < 4; j++)
                xb[j] = xok ? *(const float4*)(xrow + k0 + lk + j * 4)
                            : make_float4(0.f, 0.f, 0.f, 0.f);
            whb[0] = *(const uint4*)(whrow + k0 + lk);
            whb[1] = *(const uint4*)(whrow + k0 + lk + 8);
            wlb[0] = *(const uint4*)(wlrow + k0 + lk);
            wlb[1] = *(const uint4*)(wlrow + k0 + lk + 8);
        }

        // 2 k-steps of k=16 (scalar LDS fragment loads — fastest measured)
#pragma unroll
        for (int ks = 0; ks < 2; ks++) {
            const int k0 = ks * 16;
            uint32_t ah[2][4];
#pragma unroll
            for (int mi = 0; mi < 2; mi++) {
                const int r = wm + mi * 16;
                const __half* bh = axh + k0 + 2 * t;
                ah[mi][0] = *(const uint32_t*)(bh + (r + g)     * SH);
                ah[mi][1] = *(const uint32_t*)(bh + (r + g + 8) * SH);
                ah[mi][2] = *(const uint32_t*)(bh + (r + g)     * SH + 8);
                ah[mi][3] = *(const uint32_t*)(bh + (r + g + 8) * SH + 8);
            }
#pragma unroll
            for (int ni = 0; ni < 8; ni++) {
                const int n = wn + ni * 8 + g;
                uint32_t bh0 = *(const uint32_t*)(swh + n * SH + k0 + 2 * t);
                uint32_t bh1 = *(const uint32_t*)(swh + n * SH + k0 + 2 * t + 8);
                uint32_t bl0 = *(const uint32_t*)(swl + n * SH + k0 + 2 * t);
                uint32_t bl1 = *(const uint32_t*)(swl + n * SH + k0 + 2 * t + 8);
#pragma unroll
                for (int mi = 0; mi < 2; mi++) {
                    mma16(acc[mi][ni], ah[mi], bh0, bh1);   // xh*wh
                    mma16(acc[mi][ni], ah[mi], bl0, bl1);   // xh*wl
                }
            }
        }
    }

    // epilogue: accumulate this K-half into g_h (pre-zeroed)
#pragma unroll
    for (int mi = 0; mi < 2; mi++) {
#pragma unroll
        for (int ni = 0; ni < 8; ni++) {
            const int r = m0 + wm + mi * 16 + g;
            const int c = wn + ni * 8 + 2 * t;
            if (r < N_NODES) {
                float* dst = g_h + (size_t)r * EMB + c;
                asm volatile("red.global.add.v2.f32 [%0], {%1,%2};"
                             :: "l"(dst), "f"(acc[mi][ni][0]),
                                "f"(acc[mi][ni][1]) : "memory");
            }
            if (r + 8 < N_NODES) {
                float* dst = g_h + (size_t)(r + 8) * EMB + c;
                asm volatile("red.global.add.v2.f32 [%0], {%1,%2};"
                             :: "l"(dst), "f"(acc[mi][ni][2]),
                                "f"(acc[mi][ni][3]) : "memory");
            }
        }
    }
}

// ---------------------------------------------------------------------------
// CSR build: memset(g_cnt) -> hist -> scan x3 (fast, multi-block) -> bucket
// ---------------------------------------------------------------------------
__global__ void hist_kernel(const int* __restrict__ row) {
    int e = blockIdx.x * blockDim.x + threadIdx.x;
    if (e < N_EDGES) atomicAdd(&g_cnt[row[e]], 1);
}

#define SCAN_B 512
#define SCAN_NB ((N_NODES + SCAN_B - 1) / SCAN_B)   // 98

__global__ void scan1_kernel() {
    __shared__ int s[SCAN_B];
    int i = blockIdx.x * SCAN_B + threadIdx.x;
    int v = (i < N_NODES) ? g_cnt[i] : 0;
    s[threadIdx.x] = v;
    __syncthreads();
#pragma unroll
    for (int d = 1; d < SCAN_B; d <<= 1) {
        int tmp = (threadIdx.x >= d) ? s[threadIdx.x - d] : 0;
        __syncthreads();
        s[threadIdx.x] += tmp;
        __syncthreads();
    }
    if (i < N_NODES) g_off[i] = s[threadIdx.x] - v;
    if (threadIdx.x == SCAN_B - 1) g_part[blockIdx.x] = s[SCAN_B - 1];
}

__global__ void scan2_kernel() {
    __shared__ int s[128];
    int tid = threadIdx.x;
    int v = (tid < SCAN_NB) ? g_part[tid] : 0;
    s[tid] = v;
    __syncthreads();
#pragma unroll
    for (int d = 1; d < 128; d <<= 1) {
        int tmp = (tid >= d) ? s[tid - d] : 0;
        __syncthreads();
        s[tid] += tmp;
        __syncthreads();
    }
    if (tid < SCAN_NB) g_part[tid] = s[tid] - v;
    if (tid == 0) g_off[N_NODES] = N_EDGES;
}

__global__ void scan3_kernel() {
    int i = blockIdx.x * SCAN_B + threadIdx.x;
    if (i < N_NODES) {
        g_off[i] += g_part[blockIdx.x];
        g_cnt[i] = 0;
    }
}

__global__ void bucket_kernel(const int* __restrict__ row,
                              const int* __restrict__ col,
                              const float* __restrict__ vals) {
    int e = blockIdx.x * blockDim.x + threadIdx.x;
    if (e < N_EDGES) {
        int r = row[e];
        int pos = g_off[r] + atomicAdd(&g_cnt[r], 1);
        g_edge[pos] = make_int2(col[e], __float_as_int(vals[e]));
    }
}

// ---------------------------------------------------------------------------
// Gather: one warp per destination node; atomic-free, writes out once.
// ---------------------------------------------------------------------------
__global__ void gather_kernel(float* __restrict__ out) {
    const int lane = threadIdx.x & 31;
    const int node = (blockIdx.x * blockDim.x + threadIdx.x) >> 5;
    if (node >= N_NODES) return;

    const int beg = g_off[node];
    const int end = g_off[node + 1];

    float4 acc = make_float4(0.f, 0.f, 0.f, 0.f);
    for (int e = beg; e < end; e++) {
        const int2 ev = g_edge[e];
        const float v = __int_as_float(ev.y);
        const float4 hv = __ldg((const float4*)(g_h + (size_t)ev.x * EMB) + lane);
        acc.x = fmaf(v, hv.x, acc.x);
        acc.y = fmaf(v, hv.y, acc.y);
        acc.z = fmaf(v, hv.z, acc.z);
        acc.w = fmaf(v, hv.w, acc.w);
    }
    *((float4*)(out + (size_t)node * EMB) + lane) = acc;
}

// ---------------------------------------------------------------------------
// Launch. Host order puts GEMM at launch #6 for ncu (-s 5 -c 1):
//   split_w(1), memset h(2), memset cnt(3), hist(4), scan1(5), GEMM(6), ...
// Streams: main = split_w -> (wait h-zero) -> GEMM -> (wait CSR) -> gather
//          side = memset h, memset cnt, hist, scan1..3, bucket
// ---------------------------------------------------------------------------
extern "C" void kernel_launch(void* const* d_in, const int* in_sizes, int n_in,
                              void* d_out, int out_size) {
    const float* x    = (const float*)d_in[0];
    const float* w    = (const float*)d_in[1];
    const int*   row  = (const int*)  d_in[2];
    const int*   col  = (const int*)  d_in[3];
    const float* vals = (const float*)d_in[4];
    float*       out  = (float*)d_out;

    static cudaStream_t s_side = nullptr;
    static cudaEvent_t  ev_fork = nullptr, ev_join = nullptr, ev_hzero = nullptr;
    if (s_side == nullptr) {
        cudaStreamCreateWithFlags(&s_side, cudaStreamNonBlocking);
        cudaEventCreateWithFlags(&ev_fork,  cudaEventDisableTiming);
        cudaEventCreateWithFlags(&ev_join,  cudaEventDisableTiming);
        cudaEventCreateWithFlags(&ev_hzero, cudaEventDisableTiming);
    }

    int*   cnt_ptr = nullptr;
    float* h_ptr   = nullptr;
    cudaGetSymbolAddress((void**)&cnt_ptr, g_cnt);
    cudaGetSymbolAddress((void**)&h_ptr,   g_h);

    // (1) main: split W
    split_w_kernel<<<(EMB * FEAT + 255) / 256, 256>>>(w);

    // fork side stream
    cudaEventRecord(ev_fork, 0);
    cudaStreamWaitEvent(s_side, ev_fork, 0);

    // (2) side: zero h accumulator (needed before GEMM red-epilogue)
    cudaMemsetAsync(h_ptr, 0, (size_t)N_NODES * EMB * sizeof(float), s_side);
    cudaEventRecord(ev_hzero, s_side);
    // (3-5) side: CSR build starts
    cudaMemsetAsync(cnt_ptr, 0, N_NODES * sizeof(int), s_side);
    hist_kernel<<<(N_EDGES + 255) / 256, 256, 0, s_side>>>(row);
    scan1_kernel<<<SCAN_NB, SCAN_B, 0, s_side>>>();

    // (6) main: GEMM (K-split 2, grid 782)  <-- ncu window
    cudaStreamWaitEvent(0, ev_hzero, 0);
    gemm_fp16_mma<<<((N_NODES + 127) / 128) * 2, 256>>>(x);

    // side: finish CSR build
    scan2_kernel<<<1, 128, 0, s_side>>>();
    scan3_kernel<<<SCAN_NB, SCAN_B, 0, s_side>>>();
    bucket_kernel<<<(N_EDGES + 255) / 256, 256, 0, s_side>>>(row, col, vals);
    cudaEventRecord(ev_join, s_side);

    // join, then gather
    cudaStreamWaitEvent(0, ev_join, 0);
    gather_kernel<<<(N_NODES * 32 + 255) / 256, 256>>>(out);
}